// round 1
// baseline (speedup 1.0000x reference)
#include <cuda_runtime.h>
#include <cuda_bf16.h>
#include <math.h>

// Problem constants
#define Bsz   2
#define Npts  8192
#define Kn    3
#define NC    8            // candidate chunks (parallelism for KNN phase)
#define CHUNK (Npts / NC)  // 1024 candidates per chunk
#define TILE  128          // smem candidate tile
#define NQ    (Bsz * Npts) // 16384 total queries

// Scratch: per (query, chunk) partial top-3 (dist + idx)
__device__ float g_pd[NQ * NC * 3];
__device__ int   g_pi[NQ * NC * 3];

// ---------------------------------------------------------------------------
// Kernel 1: partial KNN. blockIdx.x = query tile (128 queries), blockIdx.y = chunk.
// Each thread owns one query, scans CHUNK candidates staged through smem,
// maintains top-3 smallest distances (strict < while scanning ascending index
// == jax.lax.top_k tie-break: smaller index wins on equal distance).
// ---------------------------------------------------------------------------
__global__ __launch_bounds__(TILE) void knn_partial_kernel(const float* __restrict__ xyz)
{
    const int tid = threadIdx.x;
    const int gq  = blockIdx.x * TILE + tid;   // global query id, 0..NQ-1
    const int ch  = blockIdx.y;                // chunk id, 0..NC-1
    const int b   = gq >> 13;                  // / Npts
    const int q   = gq & (Npts - 1);

    const float* xb = xyz + (size_t)b * Npts * 3;
    const float qx = xb[q * 3 + 0];
    const float qy = xb[q * 3 + 1];
    const float qz = xb[q * 3 + 2];

    float d0 = INFINITY, d1 = INFINITY, d2 = INFINITY;
    int   i0 = 0x7fffffff, i1 = 0x7fffffff, i2 = 0x7fffffff;

    __shared__ float sx[TILE], sy[TILE], sz[TILE];

    const int cbeg = ch * CHUNK;
    const int cend = cbeg + CHUNK;

    for (int t0 = cbeg; t0 < cend; t0 += TILE) {
        __syncthreads();
        {
            const int j = t0 + tid;
            sx[tid] = xb[j * 3 + 0];
            sy[tid] = xb[j * 3 + 1];
            sz[tid] = xb[j * 3 + 2];
        }
        __syncthreads();

        #pragma unroll 8
        for (int jj = 0; jj < TILE; jj++) {
            const float dx = qx - sx[jj];
            const float dy = qy - sy[jj];
            const float dz = qz - sz[jj];
            const float d  = fmaf(dx, dx, fmaf(dy, dy, dz * dz));
            if (d < d2) {
                const int cand = t0 + jj;
                if (d < d0)      { d2 = d1; i2 = i1; d1 = d0; i1 = i0; d0 = d; i0 = cand; }
                else if (d < d1) { d2 = d1; i2 = i1; d1 = d;  i1 = cand; }
                else             { d2 = d;  i2 = cand; }
            }
        }
    }

    const int base = (gq * NC + ch) * 3;
    g_pd[base + 0] = d0; g_pd[base + 1] = d1; g_pd[base + 2] = d2;
    g_pi[base + 0] = i0; g_pi[base + 1] = i1; g_pi[base + 2] = i2;
}

// ---------------------------------------------------------------------------
// Kernel 2: merge partials (warp per query) + gather attributes + std loss.
// 256 threads/block = 8 warps = 8 queries per block. Block-reduce, one
// atomicAdd per block.
// ---------------------------------------------------------------------------
#define K2_THREADS 256
#define K2_WARPS   (K2_THREADS / 32)

__global__ __launch_bounds__(K2_THREADS) void merge_loss_kernel(
    const float* __restrict__ rot,  // [B,N,4]
    const float* __restrict__ scl,  // [B,N,3]
    const float* __restrict__ col,  // [B,N,45]
    const float* __restrict__ opa,  // [B,N,1]
    float* __restrict__ out)
{
    const int lane = threadIdx.x & 31;
    const int wid  = threadIdx.x >> 5;
    const int gq   = blockIdx.x * K2_WARPS + wid;   // global query id
    const int b    = gq >> 13;

    // Load this query's 24 partial candidates (lanes 0..23)
    float v  = INFINITY;
    int   ix = 0x7fffffff;
    if (lane < NC * 3) {
        v  = g_pd[gq * (NC * 3) + lane];
        ix = g_pi[gq * (NC * 3) + lane];
    }

    // 3 rounds of warp lexicographic argmin (d, then idx) -> final top-3 set.
    float nd[Kn];
    int   ni[Kn];
    #pragma unroll
    for (int r = 0; r < Kn; r++) {
        float bv = v; int bi = ix;
        #pragma unroll
        for (int off = 16; off > 0; off >>= 1) {
            const float ov = __shfl_xor_sync(0xffffffffu, bv, off);
            const int   oi = __shfl_xor_sync(0xffffffffu, bi, off);
            if (ov < bv || (ov == bv && oi < bi)) { bv = ov; bi = oi; }
        }
        nd[r] = bv; ni[r] = bi;
        if (ix == bi) v = INFINITY;   // indices are unique: mask out the winner
    }

    // Global attribute rows of the 3 neighbors
    const int r0 = b * Npts + ni[0];
    const int r1 = b * Npts + ni[1];
    const int r2 = b * Npts + ni[2];

    float local = 0.0f;

    // Distance term: mean over [N,K], averaged over B
    if (lane == 0) {
        local += (nd[0] + nd[1] + nd[2]) * (1.0f / ((float)Bsz * Npts * Kn));
    }

    // 53 channels: 0..3 rot(C=4), 4..6 scales(C=3), 7 opacity(C=1), 8..52 colors(C=45)
    for (int c = lane; c < 53; c += 32) {
        const float* bp; int C; int cc;
        if (c < 4)       { bp = rot; C = 4;  cc = c;     }
        else if (c < 7)  { bp = scl; C = 3;  cc = c - 4; }
        else if (c < 8)  { bp = opa; C = 1;  cc = 0;     }
        else             { bp = col; C = 45; cc = c - 8; }

        const float x0 = __ldg(bp + (size_t)r0 * C + cc);
        const float x1 = __ldg(bp + (size_t)r1 * C + cc);
        const float x2 = __ldg(bp + (size_t)r2 * C + cc);

        const float m  = (x0 + x1 + x2) * (1.0f / 3.0f);
        const float e0 = x0 - m, e1 = x1 - m, e2 = x2 - m;
        const float var = fmaf(e0, e0, fmaf(e1, e1, e2 * e2)) * 0.5f;  // ddof=1: /(K-1)
        local += sqrtf(var) * (1.0f / ((float)Bsz * Npts * (float)C));
    }

    // Warp reduce
    #pragma unroll
    for (int off = 16; off > 0; off >>= 1)
        local += __shfl_xor_sync(0xffffffffu, local, off);

    __shared__ float red[K2_WARPS];
    if (lane == 0) red[wid] = local;
    __syncthreads();

    if (threadIdx.x < K2_WARPS) {
        float s = red[threadIdx.x];
        #pragma unroll
        for (int off = K2_WARPS / 2; off > 0; off >>= 1)
            s += __shfl_xor_sync((1u << K2_WARPS) - 1u, s, off);
        if (threadIdx.x == 0) atomicAdd(out, s);
    }
}

__global__ void zero_out_kernel(float* out) { out[0] = 0.0f; }

// ---------------------------------------------------------------------------
extern "C" void kernel_launch(void* const* d_in, const int* in_sizes, int n_in,
                              void* d_out, int out_size)
{
    const float* xyz = (const float*)d_in[0];
    const float* rot = (const float*)d_in[1];
    const float* scl = (const float*)d_in[2];
    const float* col = (const float*)d_in[3];
    const float* opa = (const float*)d_in[4];
    float* out = (float*)d_out;

    zero_out_kernel<<<1, 1>>>(out);

    dim3 g1(NQ / TILE, NC);   // (128, 8)
    knn_partial_kernel<<<g1, TILE>>>(xyz);

    merge_loss_kernel<<<NQ / K2_WARPS, K2_THREADS>>>(rot, scl, col, opa, out);
}